// round 1
// baseline (speedup 1.0000x reference)
#include <cuda_runtime.h>

// Problem constants
#define M_TOT 16384          // B*T = 4*4096
#define NDIM  512
#define NHEAD 8
#define DHEAD 64
#define NBH   32             // B*H
#define TSPLIT 8

// Scratch (alloc-free rule: __device__ globals)
__device__ float g_q[M_TOT * NDIM];
__device__ float g_k[M_TOT * NDIM];
__device__ float g_v[M_TOT * NDIM];
__device__ float g_o[M_TOT * NDIM];
__device__ float g_ctx[NBH * DHEAD * DHEAD];
__device__ float g_ksum[NBH * DHEAD];
__device__ float g_ctxp[TSPLIT * NBH * DHEAD * DHEAD];
__device__ float g_ksump[TSPLIT * NBH * DHEAD];

// ---------------------------------------------------------------------------
// GEMM: C[M,512] = A[M,512] * W[512,512]^T + bias   (C[m,n] = sum_k A[m,k]W[n,k])
// Tile: BM=128, BN=64, BK=16; 256 threads; 8x4 per-thread microtile.
// ---------------------------------------------------------------------------
__global__ __launch_bounds__(256) void gemm_bias_k(
    const float* __restrict__ A, const float* __restrict__ W,
    const float* __restrict__ bias, float* __restrict__ C)
{
    __shared__ float As[16][132];   // [k][m], padded
    __shared__ float Bs[16][68];    // [k][n], padded

    const int bm = blockIdx.y * 128;
    const int bn = blockIdx.x * 64;
    const int tid = threadIdx.x;
    const int tx = tid & 15;        // n-dir, 16 threads * 4 cols
    const int ty = tid >> 4;        // m-dir, 16 threads * 8 rows

    float acc[8][4];
#pragma unroll
    for (int i = 0; i < 8; i++)
#pragma unroll
        for (int j = 0; j < 4; j++) acc[i][j] = 0.f;

    for (int k0 = 0; k0 < 512; k0 += 16) {
        // Load A tile 128x16 (col = tx is the k index -> coalesced 64B groups)
#pragma unroll
        for (int p = 0; p < 8; p++) {
            int r = ty + p * 16;
            As[tx][r] = A[(size_t)(bm + r) * 512 + k0 + tx];
        }
        // Load W tile 64x16
#pragma unroll
        for (int p = 0; p < 4; p++) {
            int r = ty + p * 16;
            Bs[tx][r] = W[(size_t)(bn + r) * 512 + k0 + tx];
        }
        __syncthreads();

#pragma unroll
        for (int kk = 0; kk < 16; kk++) {
            float a[8], b[4];
#pragma unroll
            for (int i = 0; i < 8; i++) a[i] = As[kk][ty * 8 + i];
#pragma unroll
            for (int j = 0; j < 4; j++) b[j] = Bs[kk][tx * 4 + j];
#pragma unroll
            for (int i = 0; i < 8; i++)
#pragma unroll
                for (int j = 0; j < 4; j++) acc[i][j] += a[i] * b[j];
        }
        __syncthreads();
    }

#pragma unroll
    for (int j = 0; j < 4; j++) {
        float bv = bias[bn + tx * 4 + j];
#pragma unroll
        for (int i = 0; i < 8; i++) {
            C[(size_t)(bm + ty * 8 + i) * 512 + bn + tx * 4 + j] = acc[i][j] + bv;
        }
    }
}

// ---------------------------------------------------------------------------
// Softmax over each contiguous 64-chunk (head dim). One warp per chunk.
// Buffer is [16384, 512] = 131072 chunks of 64.
// ---------------------------------------------------------------------------
__global__ __launch_bounds__(256) void softmax64_k(float* __restrict__ buf)
{
    int warp = blockIdx.x * 8 + (threadIdx.x >> 5);
    int lane = threadIdx.x & 31;
    float* p = buf + (size_t)warp * 64;
    float a = p[lane];
    float b = p[lane + 32];
    float m = fmaxf(a, b);
#pragma unroll
    for (int o = 16; o; o >>= 1) m = fmaxf(m, __shfl_xor_sync(0xffffffffu, m, o));
    float e0 = expf(a - m);
    float e1 = expf(b - m);
    float s = e0 + e1;
#pragma unroll
    for (int o = 16; o; o >>= 1) s += __shfl_xor_sync(0xffffffffu, s, o);
    float inv = 1.f / s;
    p[lane]      = e0 * inv;
    p[lane + 32] = e1 * inv;
}

// ---------------------------------------------------------------------------
// context partials: ctx[bh][d][e] += sum_t k[t,d] v[t,e]  over a 512-slice of T
// also k_sum partials. grid (32 bh, 8 tsplit), 256 threads, 4x4 microtile.
// ---------------------------------------------------------------------------
__global__ __launch_bounds__(256) void ctx_partial_k(
    const float* __restrict__ K, const float* __restrict__ V,
    float* __restrict__ ctxp, float* __restrict__ ksump)
{
    __shared__ float ks[32][65];
    __shared__ float vs[32][65];

    const int bh = blockIdx.x;
    const int b = bh >> 3, h = bh & 7;
    const int ts = blockIdx.y;
    const int tid = threadIdx.x;
    const int tx = tid & 15;       // e
    const int ty = tid >> 4;       // d
    const int col = tid & 63;      // load mapping
    const int trow = tid >> 6;     // 4 t-rows per pass

    float acc[4][4];
#pragma unroll
    for (int i = 0; i < 4; i++)
#pragma unroll
        for (int j = 0; j < 4; j++) acc[i][j] = 0.f;
    float ksacc[4] = {0.f, 0.f, 0.f, 0.f};

    const int rowbase = b * 4096 + ts * 512;

    for (int tt = 0; tt < 512; tt += 32) {
#pragma unroll
        for (int p = 0; p < 8; p++) {
            int t = trow + p * 4;
            size_t gidx = (size_t)(rowbase + tt + t) * 512 + h * 64 + col;
            ks[t][col] = K[gidx];
            vs[t][col] = V[gidx];
        }
        __syncthreads();
#pragma unroll
        for (int t = 0; t < 32; t++) {
            float a[4], bb[4];
#pragma unroll
            for (int i = 0; i < 4; i++) a[i] = ks[t][ty * 4 + i];
#pragma unroll
            for (int j = 0; j < 4; j++) bb[j] = vs[t][tx * 4 + j];
#pragma unroll
            for (int i = 0; i < 4; i++)
#pragma unroll
                for (int j = 0; j < 4; j++) acc[i][j] += a[i] * bb[j];
            if (tx == 0) {
#pragma unroll
                for (int i = 0; i < 4; i++) ksacc[i] += a[i];
            }
        }
        __syncthreads();
    }

    float* cp = ctxp + (size_t)(ts * NBH + bh) * 4096;
#pragma unroll
    for (int i = 0; i < 4; i++)
#pragma unroll
        for (int j = 0; j < 4; j++)
            cp[(ty * 4 + i) * 64 + tx * 4 + j] = acc[i][j];
    if (tx == 0) {
#pragma unroll
        for (int i = 0; i < 4; i++)
            ksump[(size_t)(ts * NBH + bh) * 64 + ty * 4 + i] = ksacc[i];
    }
}

__global__ void reduce_ctx_k(const float* __restrict__ ctxp, float* __restrict__ ctx)
{
    int i = blockIdx.x * blockDim.x + threadIdx.x;
    if (i < NBH * 4096) {
        float s = 0.f;
#pragma unroll
        for (int p = 0; p < TSPLIT; p++) s += ctxp[(size_t)p * NBH * 4096 + i];
        ctx[i] = s;
    }
}

__global__ void reduce_ksum_k(const float* __restrict__ ksump, float* __restrict__ ksum)
{
    int i = blockIdx.x * blockDim.x + threadIdx.x;
    if (i < NBH * 64) {
        float s = 0.f;
#pragma unroll
        for (int p = 0; p < TSPLIT; p++) s += ksump[(size_t)p * NBH * 64 + i];
        ksum[i] = s;
    }
}

// ---------------------------------------------------------------------------
// out = (q @ ctx) * Dinv + q, Dinv = 1/(q . ksum).
// grid (32 bh, 64 row-tiles of 64), 256 threads: 4 threads/row, 16 e's each.
// Writes interim in [B,T,512] layout.
// ---------------------------------------------------------------------------
__global__ __launch_bounds__(256) void attn_out_k(
    const float* __restrict__ Q, const float* __restrict__ ctx,
    const float* __restrict__ ksum, float* __restrict__ O)
{
    __shared__ float cs[64][64];
    __shared__ float qs[64][65];
    __shared__ float kss[64];

    const int bh = blockIdx.x;
    const int b = bh >> 3, h = bh & 7;
    const int tb = blockIdx.y;
    const int tid = threadIdx.x;

    const float* cg = ctx + (size_t)bh * 4096;
    for (int i = tid; i < 4096; i += 256) cs[i >> 6][i & 63] = cg[i];
    if (tid < 64) kss[tid] = ksum[bh * 64 + tid];

    const int rowbase = b * 4096 + tb * 64;
    const int col = tid & 63;
    const int rr = tid >> 6;
#pragma unroll
    for (int p = 0; p < 16; p++) {
        int r = rr + p * 4;
        qs[r][col] = Q[(size_t)(rowbase + r) * 512 + h * 64 + col];
    }
    __syncthreads();

    const int r = tid >> 2;
    const int e0 = (tid & 3) * 16;
    float acc[16];
#pragma unroll
    for (int j = 0; j < 16; j++) acc[j] = 0.f;
    float dv = 0.f;
#pragma unroll
    for (int d = 0; d < 64; d++) {
        float qv = qs[r][d];
        dv += qv * kss[d];
#pragma unroll
        for (int j = 0; j < 16; j++) acc[j] += qv * cs[d][e0 + j];
    }
    float Dinv = 1.f / dv;
    float* op = O + (size_t)(rowbase + r) * 512 + h * 64 + e0;
#pragma unroll
    for (int j = 0; j < 16; j++) op[j] = acc[j] * Dinv + qs[r][e0 + j];
}

// ---------------------------------------------------------------------------
extern "C" void kernel_launch(void* const* d_in, const int* in_sizes, int n_in,
                              void* d_out, int out_size)
{
    const float* x  = (const float*)d_in[0];
    const float* Wq = (const float*)d_in[1];
    const float* bq = (const float*)d_in[2];
    const float* Wk = (const float*)d_in[3];
    const float* bk = (const float*)d_in[4];
    const float* Wv = (const float*)d_in[5];
    const float* bv = (const float*)d_in[6];
    const float* Wp = (const float*)d_in[7];
    const float* bp = (const float*)d_in[8];
    float* out = (float*)d_out;

    float *q, *k, *v, *o, *ctx, *ksum, *ctxp, *ksump;
    cudaGetSymbolAddress((void**)&q, g_q);
    cudaGetSymbolAddress((void**)&k, g_k);
    cudaGetSymbolAddress((void**)&v, g_v);
    cudaGetSymbolAddress((void**)&o, g_o);
    cudaGetSymbolAddress((void**)&ctx, g_ctx);
    cudaGetSymbolAddress((void**)&ksum, g_ksum);
    cudaGetSymbolAddress((void**)&ctxp, g_ctxp);
    cudaGetSymbolAddress((void**)&ksump, g_ksump);

    dim3 gg(8, 128);   // N/64, M/128

    gemm_bias_k<<<gg, 256>>>(x, Wq, bq, q);
    gemm_bias_k<<<gg, 256>>>(x, Wk, bk, k);
    gemm_bias_k<<<gg, 256>>>(x, Wv, bv, v);

    softmax64_k<<<16384, 256>>>(q);   // 131072 chunks / 8 warps per block
    softmax64_k<<<16384, 256>>>(k);

    ctx_partial_k<<<dim3(NBH, TSPLIT), 256>>>(k, v, ctxp, ksump);
    reduce_ctx_k<<<(NBH * 4096 + 255) / 256, 256>>>(ctxp, ctx);
    reduce_ksum_k<<<(NBH * 64 + 255) / 256, 256>>>(ksump, ksum);

    attn_out_k<<<dim3(NBH, 64), 256>>>(q, ctx, ksum, o);

    gemm_bias_k<<<gg, 256>>>(o, Wp, bp, out);
}

// round 3
// speedup vs baseline: 2.0970x; 2.0970x over previous
#include <cuda_runtime.h>
#include <cuda_bf16.h>
#include <cstdint>

// Problem constants
#define M_TOT 16384          // B*T
#define NDIM  512
#define NBH   32             // B*H
#define TSPLIT 32

// ---------------- scratch (__device__ globals; no allocation allowed) -------
__device__ float g_q[M_TOT * NDIM];
__device__ float g_k[M_TOT * NDIM];
__device__ float g_v[M_TOT * NDIM];
__device__ float g_ctx[NBH * 64 * 64];
__device__ float g_ksum[NBH * 64];
__device__ float g_ctxp[TSPLIT * NBH * 64 * 64];
__device__ float g_ksump[TSPLIT * NBH * 64];
__device__ __nv_bfloat16 g_xh[M_TOT * NDIM];
__device__ __nv_bfloat16 g_xl[M_TOT * NDIM];
__device__ __nv_bfloat16 g_oh[M_TOT * NDIM];
__device__ __nv_bfloat16 g_ol[M_TOT * NDIM];
__device__ __nv_bfloat16 g_wh[4 * NDIM * NDIM];
__device__ __nv_bfloat16 g_wl[4 * NDIM * NDIM];

// ---------------- helpers ---------------------------------------------------
__device__ __forceinline__ uint32_t smem_u32(const void* p) {
    uint32_t a;
    asm("{ .reg .u64 t; cvta.to.shared.u64 t, %1; cvt.u32.u64 %0, t; }" : "=r"(a) : "l"(p));
    return a;
}
#define SWZ(o) ((o) ^ (((o) >> 3) & 0x70))

__device__ __forceinline__ void cp16(uint32_t dst, const void* src) {
    asm volatile("cp.async.cg.shared.global [%0], [%1], 16;" :: "r"(dst), "l"(src));
}
#define CP_COMMIT() asm volatile("cp.async.commit_group;" ::: "memory")
#define CP_WAIT(n)  asm volatile("cp.async.wait_group %0;" :: "n"(n) : "memory")

#define LDSM4(r, addr) \
    asm volatile("ldmatrix.sync.aligned.m8n8.x4.shared.b16 {%0,%1,%2,%3}, [%4];" \
        : "=r"((r)[0]), "=r"((r)[1]), "=r"((r)[2]), "=r"((r)[3]) : "r"(addr))

#define MMA_BF16(d, a, b0, b1) \
    asm volatile("mma.sync.aligned.m16n8k16.row.col.f32.bf16.bf16.f32 " \
        "{%0,%1,%2,%3}, {%4,%5,%6,%7}, {%8,%9}, {%0,%1,%2,%3};" \
        : "+f"((d)[0]), "+f"((d)[1]), "+f"((d)[2]), "+f"((d)[3]) \
        : "r"((a)[0]), "r"((a)[1]), "r"((a)[2]), "r"((a)[3]), "r"(b0), "r"(b1))

// ---------------------------------------------------------------------------
// HMMA GEMM: C[M,512] = (Ah+Al)[M,512] * (Wh+Wl)[512,512]^T + bias
// Virtual K = 1536: chunks 0-7 Ah*Bh, 8-15 Al*Bh, 16-23 Ah*Bl.
// Tile BM=128, BN=128, BK=64. 256 threads = 8 warps (4m x 2n), warp 32x64.
// 3-stage cp.async pipeline, SW128-swizzled smem, ldmatrix feeds.
// ---------------------------------------------------------------------------
#define BKB   128            // bytes per smem row (64 bf16)
#define A_BYTES (128 * BKB)  // 16KB
#define STG   (2 * A_BYTES)  // 32KB per stage (A + B)
#define NSTG  3
#define SMEM_GEMM (NSTG * STG)
#define CHUNKS 24

struct GemmArgs {
    const __nv_bfloat16 *Ah, *Al, *Bh, *Bl;
    const float* bias;
    float* C;
};

__device__ __forceinline__ void load_chunk(
    uint32_t sbase, int stage, int chunk, int bm, int bn, int tid,
    const __nv_bfloat16* Ah, const __nv_bfloat16* Al,
    const __nv_bfloat16* Bh, const __nv_bfloat16* Bl)
{
    const int term = chunk >> 3;
    const int k0 = (chunk & 7) * 64;
    const __nv_bfloat16* As = (term == 1) ? Al : Ah;
    const __nv_bfloat16* Bs = (term == 2) ? Bl : Bh;
    uint32_t sA = sbase + stage * STG;
    uint32_t sB = sA + A_BYTES;
#pragma unroll
    for (int t = 0; t < 4; t++) {
        int idx = tid + t * 256;                  // 1024 x 16B for A
        int row = idx >> 3, c = idx & 7;
        cp16(sA + SWZ((uint32_t)(row * BKB + c * 16)),
             As + (size_t)(bm + row) * 512 + k0 + c * 8);
    }
#pragma unroll
    for (int t = 0; t < 4; t++) {
        int idx = tid + t * 256;                  // 1024 x 16B for B
        int row = idx >> 3, c = idx & 7;
        cp16(sB + SWZ((uint32_t)(row * BKB + c * 16)),
             Bs + (size_t)(bn + row) * 512 + k0 + c * 8);
    }
}

__global__ __launch_bounds__(256, 2) void mma_gemm_k(GemmArgs args)
{
    extern __shared__ char smem[];
    uint32_t sbase = smem_u32(smem);

    const int tid = threadIdx.x;
    const int wid = tid >> 5;
    const int lane = tid & 31;
    const int wm = (wid & 3) * 32;       // warp m offset
    const int wn = (wid >> 2) * 64;      // warp n offset
    const int bm = blockIdx.y * 128;
    const int bn = blockIdx.x * 128;

    float acc[2][8][4];
#pragma unroll
    for (int i = 0; i < 2; i++)
#pragma unroll
        for (int j = 0; j < 8; j++)
#pragma unroll
            for (int p = 0; p < 4; p++) acc[i][j][p] = 0.f;

    // ldmatrix per-thread address components
    const int a_row = wm + (lane & 15);
    const int a_cb  = (lane >> 4) * 16;
    const int b_row = wn + (lane & 7) + ((lane >> 4) & 1) * 8;
    const int b_cb  = ((lane >> 3) & 1) * 16;

    // prologue: chunks 0,1
    load_chunk(sbase, 0, 0, bm, bn, tid, args.Ah, args.Al, args.Bh, args.Bl);
    CP_COMMIT();
    load_chunk(sbase, 1, 1, bm, bn, tid, args.Ah, args.Al, args.Bh, args.Bl);
    CP_COMMIT();

    for (int i = 0; i < CHUNKS; i++) {
        CP_WAIT(1);
        __syncthreads();
        if (i + 2 < CHUNKS)
            load_chunk(sbase, (i + 2) % NSTG, i + 2, bm, bn, tid,
                       args.Ah, args.Al, args.Bh, args.Bl);
        CP_COMMIT();

        uint32_t sA = sbase + (i % NSTG) * STG;
        uint32_t sB = sA + A_BYTES;
#pragma unroll
        for (int ks = 0; ks < 4; ks++) {
            uint32_t a[2][4];
#pragma unroll
            for (int mi = 0; mi < 2; mi++) {
                uint32_t addr = sA + SWZ((uint32_t)((a_row + mi * 16) * BKB + ks * 32 + a_cb));
                LDSM4(a[mi], addr);
            }
            uint32_t b[4][4];
#pragma unroll
            for (int nb = 0; nb < 4; nb++) {
                uint32_t addr = sB + SWZ((uint32_t)((b_row + nb * 16) * BKB + ks * 32 + b_cb));
                LDSM4(b[nb], addr);
            }
#pragma unroll
            for (int mi = 0; mi < 2; mi++)
#pragma unroll
                for (int nb = 0; nb < 4; nb++) {
                    MMA_BF16(acc[mi][nb * 2 + 0], a[mi], b[nb][0], b[nb][1]);
                    MMA_BF16(acc[mi][nb * 2 + 1], a[mi], b[nb][2], b[nb][3]);
                }
        }
    }

    // epilogue: acc + bias -> C (fp32)
    const int r0 = bm + wm + (lane >> 2);
    const int c0 = bn + wn + (lane & 3) * 2;
#pragma unroll
    for (int nf = 0; nf < 8; nf++) {
        int col = c0 + nf * 8;
        float bb0 = __ldg(args.bias + col);
        float bb1 = __ldg(args.bias + col + 1);
#pragma unroll
        for (int mi = 0; mi < 2; mi++) {
            int row = r0 + mi * 16;
            float2 v0 = {acc[mi][nf][0] + bb0, acc[mi][nf][1] + bb1};
            float2 v1 = {acc[mi][nf][2] + bb0, acc[mi][nf][3] + bb1};
            *(float2*)(args.C + (size_t)row * 512 + col) = v0;
            *(float2*)(args.C + (size_t)(row + 8) * 512 + col) = v1;
        }
    }
}

// ---------------------------------------------------------------------------
// fp32 -> bf16 hi/lo split
// ---------------------------------------------------------------------------
__global__ __launch_bounds__(256) void split_k(
    const float* __restrict__ s, __nv_bfloat16* __restrict__ h,
    __nv_bfloat16* __restrict__ l, int n)
{
    int i = (blockIdx.x * 256 + threadIdx.x) * 4;
    if (i < n) {
        float4 v = *(const float4*)(s + i);
        __nv_bfloat16 h0 = __float2bfloat16(v.x), h1 = __float2bfloat16(v.y);
        __nv_bfloat16 h2 = __float2bfloat16(v.z), h3 = __float2bfloat16(v.w);
        __nv_bfloat162 hh0{h0, h1}, hh1{h2, h3};
        __nv_bfloat162 ll0{__float2bfloat16(v.x - __bfloat162float(h0)),
                           __float2bfloat16(v.y - __bfloat162float(h1))};
        __nv_bfloat162 ll1{__float2bfloat16(v.z - __bfloat162float(h2)),
                           __float2bfloat16(v.w - __bfloat162float(h3))};
        *(__nv_bfloat162*)(h + i) = hh0; *(__nv_bfloat162*)(h + i + 2) = hh1;
        *(__nv_bfloat162*)(l + i) = ll0; *(__nv_bfloat162*)(l + i + 2) = ll1;
    }
}

// ---------------------------------------------------------------------------
// softmax over contiguous 64-chunks (head dim); one warp per chunk
// ---------------------------------------------------------------------------
__global__ __launch_bounds__(256) void softmax64_k(float* __restrict__ buf)
{
    int warp = blockIdx.x * 8 + (threadIdx.x >> 5);
    int lane = threadIdx.x & 31;
    float* p = buf + (size_t)warp * 64;
    float a = p[lane], b = p[lane + 32];
    float m = fmaxf(a, b);
#pragma unroll
    for (int o = 16; o; o >>= 1) m = fmaxf(m, __shfl_xor_sync(0xffffffffu, m, o));
    float e0 = expf(a - m), e1 = expf(b - m);
    float s = e0 + e1;
#pragma unroll
    for (int o = 16; o; o >>= 1) s += __shfl_xor_sync(0xffffffffu, s, o);
    float inv = 1.f / s;
    p[lane] = e0 * inv; p[lane + 32] = e1 * inv;
}

// ---------------------------------------------------------------------------
// context partials + k_sum partials (fp32); T slice of 128 per block
// ---------------------------------------------------------------------------
__global__ __launch_bounds__(256) void ctx_partial_k(
    const float* __restrict__ K, const float* __restrict__ V,
    float* __restrict__ ctxp, float* __restrict__ ksump)
{
    __shared__ float ks[32][65];
    __shared__ float vs[32][65];
    const int bh = blockIdx.x, b = bh >> 3, h = bh & 7;
    const int ts = blockIdx.y, tid = threadIdx.x;
    const int tx = tid & 15, ty = tid >> 4;
    const int col = tid & 63, trow = tid >> 6;

    float acc[4][4];
#pragma unroll
    for (int i = 0; i < 4; i++)
#pragma unroll
        for (int j = 0; j < 4; j++) acc[i][j] = 0.f;
    float ksacc[4] = {0.f, 0.f, 0.f, 0.f};
    const int rowbase = b * 4096 + ts * 128;

    for (int tt = 0; tt < 128; tt += 32) {
#pragma unroll
        for (int p = 0; p < 8; p++) {
            int t = trow + p * 4;
            size_t g = (size_t)(rowbase + tt + t) * 512 + h * 64 + col;
            ks[t][col] = K[g]; vs[t][col] = V[g];
        }
        __syncthreads();
#pragma unroll
        for (int t = 0; t < 32; t++) {
            float a[4], bb[4];
#pragma unroll
            for (int i = 0; i < 4; i++) a[i] = ks[t][ty * 4 + i];
#pragma unroll
            for (int j = 0; j < 4; j++) bb[j] = vs[t][tx * 4 + j];
#pragma unroll
            for (int i = 0; i < 4; i++)
#pragma unroll
                for (int j = 0; j < 4; j++) acc[i][j] += a[i] * bb[j];
            if (tx == 0)
#pragma unroll
                for (int i = 0; i < 4; i++) ksacc[i] += a[i];
        }
        __syncthreads();
    }
    float* cp = ctxp + (size_t)(ts * NBH + bh) * 4096;
#pragma unroll
    for (int i = 0; i < 4; i++)
#pragma unroll
        for (int j = 0; j < 4; j++)
            cp[(ty * 4 + i) * 64 + tx * 4 + j] = acc[i][j];
    if (tx == 0)
#pragma unroll
        for (int i = 0; i < 4; i++)
            ksump[(size_t)(ts * NBH + bh) * 64 + ty * 4 + i] = ksacc[i];
}

__global__ void reduce_ctx_k(const float* __restrict__ ctxp, float* __restrict__ ctx)
{
    int i = blockIdx.x * blockDim.x + threadIdx.x;
    if (i < NBH * 4096) {
        float s = 0.f;
#pragma unroll
        for (int p = 0; p < TSPLIT; p++) s += ctxp[(size_t)p * NBH * 4096 + i];
        ctx[i] = s;
    }
}
__global__ void reduce_ksum_k(const float* __restrict__ ksump, float* __restrict__ ksum)
{
    int i = blockIdx.x * blockDim.x + threadIdx.x;
    if (i < NBH * 64) {
        float s = 0.f;
#pragma unroll
        for (int p = 0; p < TSPLIT; p++) s += ksump[(size_t)p * NBH * 64 + i];
        ksum[i] = s;
    }
}

// ---------------------------------------------------------------------------
// out = (q @ ctx) * Dinv + q  -> written as bf16 hi/lo for final GEMM
// ---------------------------------------------------------------------------
__global__ __launch_bounds__(256) void attn_out_k(
    const float* __restrict__ Q, const float* __restrict__ ctx,
    const float* __restrict__ ksum,
    __nv_bfloat16* __restrict__ Oh, __nv_bfloat16* __restrict__ Ol)
{
    __shared__ float cs[64][64];
    __shared__ float qs[64][65];
    __shared__ float kss[64];
    const int bh = blockIdx.x, b = bh >> 3, h = bh & 7;
    const int tb = blockIdx.y, tid = threadIdx.x;

    const float* cg = ctx + (size_t)bh * 4096;
    for (int i = tid; i < 4096; i += 256) cs[i >> 6][i & 63] = cg[i];
    if (tid < 64) kss[tid] = ksum[bh * 64 + tid];

    const int rowbase = b * 4096 + tb * 64;
    const int col = tid & 63, rr = tid >> 6;
#pragma unroll
    for (int p = 0; p < 16; p++) {
        int r = rr + p * 4;
        qs[r][col] = Q[(size_t)(rowbase + r) * 512 + h * 64 + col];
    }
    __syncthreads();

    const int r = tid >> 2, e0 = (tid & 3) * 16;
    float acc[16];
#pragma unroll
    for (int j = 0; j < 16; j++) acc[j] = 0.f;
    float dv = 0.f;
#pragma unroll
    for (int d = 0; d < 64; d++) {
        float qv = qs[r][d];
        dv += qv * kss[d];
#pragma unroll
        for (int j = 0; j < 16; j++) acc[j] += qv * cs[d][e0 + j];
    }
    float Dinv = 1.f / dv;
    size_t base = (size_t)(rowbase + r) * 512 + h * 64 + e0;
#pragma unroll
    for (int j = 0; j < 16; j++) {
        float val = acc[j] * Dinv + qs[r][e0 + j];
        __nv_bfloat16 hh = __float2bfloat16(val);
        Oh[base + j] = hh;
        Ol[base + j] = __float2bfloat16(val - __bfloat162float(hh));
    }
}

// ---------------------------------------------------------------------------
extern "C" void kernel_launch(void* const* d_in, const int* in_sizes, int n_in,
                              void* d_out, int out_size)
{
    const float* x  = (const float*)d_in[0];
    const float* Wq = (const float*)d_in[1];
    const float* bq = (const float*)d_in[2];
    const float* Wk = (const float*)d_in[3];
    const float* bk = (const float*)d_in[4];
    const float* Wv = (const float*)d_in[5];
    const float* bv = (const float*)d_in[6];
    const float* Wp = (const float*)d_in[7];
    const float* bp = (const float*)d_in[8];
    float* out = (float*)d_out;

    float *q, *k, *v, *ctx, *ksum, *ctxp, *ksump;
    __nv_bfloat16 *xh, *xl, *oh, *ol, *wh, *wl;
    cudaGetSymbolAddress((void**)&q, g_q);
    cudaGetSymbolAddress((void**)&k, g_k);
    cudaGetSymbolAddress((void**)&v, g_v);
    cudaGetSymbolAddress((void**)&ctx, g_ctx);
    cudaGetSymbolAddress((void**)&ksum, g_ksum);
    cudaGetSymbolAddress((void**)&ctxp, g_ctxp);
    cudaGetSymbolAddress((void**)&ksump, g_ksump);
    cudaGetSymbolAddress((void**)&xh, g_xh);
    cudaGetSymbolAddress((void**)&xl, g_xl);
    cudaGetSymbolAddress((void**)&oh, g_oh);
    cudaGetSymbolAddress((void**)&ol, g_ol);
    cudaGetSymbolAddress((void**)&wh, g_wh);
    cudaGetSymbolAddress((void**)&wl, g_wl);

    cudaFuncSetAttribute(mma_gemm_k, cudaFuncAttributeMaxDynamicSharedMemorySize,
                         SMEM_GEMM);

    const int NW = NDIM * NDIM;   // 262144

    // hi/lo conversions
    split_k<<<(M_TOT * NDIM) / 4 / 256, 256>>>(x, xh, xl, M_TOT * NDIM);
    split_k<<<NW / 4 / 256, 256>>>(Wq, wh + 0 * NW, wl + 0 * NW, NW);
    split_k<<<NW / 4 / 256, 256>>>(Wk, wh + 1 * NW, wl + 1 * NW, NW);
    split_k<<<NW / 4 / 256, 256>>>(Wv, wh + 2 * NW, wl + 2 * NW, NW);
    split_k<<<NW / 4 / 256, 256>>>(Wp, wh + 3 * NW, wl + 3 * NW, NW);

    dim3 gg(4, 128);   // (N/128, M/128)
    GemmArgs aq{xh, xl, wh + 0 * NW, wl + 0 * NW, bq, q};
    GemmArgs ak{xh, xl, wh + 1 * NW, wl + 1 * NW, bk, k};
    GemmArgs av{xh, xl, wh + 2 * NW, wl + 2 * NW, bv, v};
    mma_gemm_k<<<gg, 256, SMEM_GEMM>>>(aq);
    mma_gemm_k<<<gg, 256, SMEM_GEMM>>>(ak);
    mma_gemm_k<<<gg, 256, SMEM_GEMM>>>(av);

    softmax64_k<<<16384, 256>>>(q);
    softmax64_k<<<16384, 256>>>(k);

    ctx_partial_k<<<dim3(NBH, TSPLIT), 256>>>(k, v, ctxp, ksump);
    reduce_ctx_k<<<(NBH * 4096 + 255) / 256, 256>>>(ctxp, ctx);
    reduce_ksum_k<<<(NBH * 64 + 255) / 256, 256>>>(ksump, ksum);

    attn_out_k<<<dim3(NBH, 64), 256>>>(q, ctx, ksum, oh, ol);

    GemmArgs ap{oh, ol, wh + 3 * NW, wl + 3 * NW, bp, out};
    mma_gemm_k<<<gg, 256, SMEM_GEMM>>>(ap);
}

// round 4
// speedup vs baseline: 2.3259x; 1.1091x over previous
#include <cuda_runtime.h>
#include <cuda_bf16.h>
#include <cstdint>

// Problem constants
#define M_TOT 16384          // B*T
#define NDIM  512
#define NBH   32             // B*H
#define TSPLIT 32

// ---------------- scratch (__device__ globals; no allocation allowed) -------
__device__ float g_q[M_TOT * NDIM];
__device__ float g_k[M_TOT * NDIM];
__device__ float g_v[M_TOT * NDIM];
__device__ float g_ctx[NBH * 64 * 64];
__device__ float g_ksum[NBH * 64];
__device__ float g_ctxp[TSPLIT * NBH * 64 * 64];
__device__ float g_ksump[TSPLIT * NBH * 64];
__device__ __nv_bfloat16 g_xh[M_TOT * NDIM];
__device__ __nv_bfloat16 g_xl[M_TOT * NDIM];
__device__ __nv_bfloat16 g_oh[M_TOT * NDIM];
__device__ __nv_bfloat16 g_ol[M_TOT * NDIM];
__device__ __nv_bfloat16 g_wh[4 * NDIM * NDIM];
__device__ __nv_bfloat16 g_wl[4 * NDIM * NDIM];

// ---------------- helpers ---------------------------------------------------
__device__ __forceinline__ uint32_t smem_u32(const void* p) {
    uint32_t a;
    asm("{ .reg .u64 t; cvta.to.shared.u64 t, %1; cvt.u32.u64 %0, t; }" : "=r"(a) : "l"(p));
    return a;
}
#define SWZ(o) ((o) ^ (((o) >> 3) & 0x70))

__device__ __forceinline__ void cp16(uint32_t dst, const void* src) {
    asm volatile("cp.async.cg.shared.global [%0], [%1], 16;" :: "r"(dst), "l"(src));
}
#define CP_COMMIT() asm volatile("cp.async.commit_group;" ::: "memory")
#define CP_WAIT(n)  asm volatile("cp.async.wait_group %0;" :: "n"(n) : "memory")

#define LDSM4(r, addr) \
    asm volatile("ldmatrix.sync.aligned.m8n8.x4.shared.b16 {%0,%1,%2,%3}, [%4];" \
        : "=r"((r)[0]), "=r"((r)[1]), "=r"((r)[2]), "=r"((r)[3]) : "r"(addr))

#define MMA_BF16(d, a, b0, b1) \
    asm volatile("mma.sync.aligned.m16n8k16.row.col.f32.bf16.bf16.f32 " \
        "{%0,%1,%2,%3}, {%4,%5,%6,%7}, {%8,%9}, {%0,%1,%2,%3};" \
        : "+f"((d)[0]), "+f"((d)[1]), "+f"((d)[2]), "+f"((d)[3]) \
        : "r"((a)[0]), "r"((a)[1]), "r"((a)[2]), "r"((a)[3]), "r"(b0), "r"(b1))

// ---------------------------------------------------------------------------
// HMMA GEMM with hi/lo bf16 split (virtual K=1536: AhBh, AlBh, AhBl) and
// optional fused per-head softmax epilogue.
// Tile BM=128, BN=128, BK=64; 8 warps (4m x 2n), warp tile 32x64.
// In FUSED mode: grid.x = 12 covers N=1536 concat [Wq|Wk|Wv]; slices 0,1 get
// softmax over each 64-col head chunk (entirely within one warp), slice 2 plain.
// In plain mode: grid.x = 4, slice 0 only.
// ---------------------------------------------------------------------------
#define BKB   128            // bytes per smem row (64 bf16)
#define A_BYTES (128 * BKB)  // 16KB
#define STG   (2 * A_BYTES)  // 32KB per stage (A + B)
#define NSTG  3
#define SMEM_GEMM (NSTG * STG)
#define CHUNKS 24

struct GArgs {
    const __nv_bfloat16 *Ah, *Al, *Wh, *Wl;   // Wh/Wl: base of (multi-)slice weights
    const float *b0, *b1, *b2;                // bias per 512-col slice
    float *o0, *o1, *o2;                      // output per 512-col slice
};

__device__ __forceinline__ void load_chunk(
    uint32_t sbase, int stage, int chunk, int bm, int bnn, int tid,
    const __nv_bfloat16* Ah, const __nv_bfloat16* Al,
    const __nv_bfloat16* Bh, const __nv_bfloat16* Bl)
{
    const int term = chunk >> 3;
    const int k0 = (chunk & 7) * 64;
    const __nv_bfloat16* As = (term == 1) ? Al : Ah;
    const __nv_bfloat16* Bs = (term == 2) ? Bl : Bh;
    uint32_t sA = sbase + stage * STG;
    uint32_t sB = sA + A_BYTES;
#pragma unroll
    for (int t = 0; t < 4; t++) {
        int idx = tid + t * 256;                  // 1024 x 16B for A
        int row = idx >> 3, c = idx & 7;
        cp16(sA + SWZ((uint32_t)(row * BKB + c * 16)),
             As + (size_t)(bm + row) * 512 + k0 + c * 8);
    }
#pragma unroll
    for (int t = 0; t < 4; t++) {
        int idx = tid + t * 256;                  // 1024 x 16B for B
        int row = idx >> 3, c = idx & 7;
        cp16(sB + SWZ((uint32_t)(row * BKB + c * 16)),
             Bs + (size_t)(bnn + row) * 512 + k0 + c * 8);
    }
}

template <bool FUSED>
__global__ __launch_bounds__(256, 2) void mma_gemm_k(GArgs args)
{
    extern __shared__ char smem[];
    uint32_t sbase = smem_u32(smem);

    const int tid = threadIdx.x;
    const int wid = tid >> 5;
    const int lane = tid & 31;
    const int wm = (wid & 3) * 32;       // warp m offset
    const int wn = (wid >> 2) * 64;      // warp n offset
    const int bm = blockIdx.y * 128;
    const int bn = blockIdx.x * 128;
    const int slice = bn >> 9;           // which 512-col slice (0..2)
    const int bnn = bn & 511;            // col offset within slice

    const __nv_bfloat16* Bh = args.Wh + (size_t)slice * NDIM * NDIM;
    const __nv_bfloat16* Bl = args.Wl + (size_t)slice * NDIM * NDIM;
    const float* bias = (slice == 0) ? args.b0 : (slice == 1) ? args.b1 : args.b2;
    float* Cout       = (slice == 0) ? args.o0 : (slice == 1) ? args.o1 : args.o2;
    const bool do_sm = FUSED && (slice < 2);

    float acc[2][8][4];
#pragma unroll
    for (int i = 0; i < 2; i++)
#pragma unroll
        for (int j = 0; j < 8; j++)
#pragma unroll
            for (int p = 0; p < 4; p++) acc[i][j][p] = 0.f;

    const int a_row = wm + (lane & 15);
    const int a_cb  = (lane >> 4) * 16;
    const int b_row = wn + (lane & 7) + ((lane >> 4) & 1) * 8;
    const int b_cb  = ((lane >> 3) & 1) * 16;

    load_chunk(sbase, 0, 0, bm, bnn, tid, args.Ah, args.Al, Bh, Bl);
    CP_COMMIT();
    load_chunk(sbase, 1, 1, bm, bnn, tid, args.Ah, args.Al, Bh, Bl);
    CP_COMMIT();

    for (int i = 0; i < CHUNKS; i++) {
        CP_WAIT(1);
        __syncthreads();
        if (i + 2 < CHUNKS)
            load_chunk(sbase, (i + 2) % NSTG, i + 2, bm, bnn, tid,
                       args.Ah, args.Al, Bh, Bl);
        CP_COMMIT();

        uint32_t sA = sbase + (i % NSTG) * STG;
        uint32_t sB = sA + A_BYTES;
#pragma unroll
        for (int ks = 0; ks < 4; ks++) {
            uint32_t a[2][4];
#pragma unroll
            for (int mi = 0; mi < 2; mi++) {
                uint32_t addr = sA + SWZ((uint32_t)((a_row + mi * 16) * BKB + ks * 32 + a_cb));
                LDSM4(a[mi], addr);
            }
            uint32_t b[4][4];
#pragma unroll
            for (int nb = 0; nb < 4; nb++) {
                uint32_t addr = sB + SWZ((uint32_t)((b_row + nb * 16) * BKB + ks * 32 + b_cb));
                LDSM4(b[nb], addr);
            }
#pragma unroll
            for (int mi = 0; mi < 2; mi++)
#pragma unroll
                for (int nb = 0; nb < 4; nb++) {
                    MMA_BF16(acc[mi][nb * 2 + 0], a[mi], b[nb][0], b[nb][1]);
                    MMA_BF16(acc[mi][nb * 2 + 1], a[mi], b[nb][2], b[nb][3]);
                }
        }
    }

    // ---- epilogue: bias, optional per-head softmax, store -----------------
#pragma unroll
    for (int nf = 0; nf < 8; nf++) {
        int col = bnn + wn + (lane & 3) * 2 + nf * 8;
        float bb0 = __ldg(bias + col);
        float bb1 = __ldg(bias + col + 1);
#pragma unroll
        for (int mi = 0; mi < 2; mi++) {
            acc[mi][nf][0] += bb0; acc[mi][nf][1] += bb1;
            acc[mi][nf][2] += bb0; acc[mi][nf][3] += bb1;
        }
    }

    if (do_sm) {
        // softmax over the warp's 64 cols, per row. Row owned by a lane quad
        // (lane>>2 fixed, lane&3 varies) -> shfl_xor 1,2 reduces the quad.
#pragma unroll
        for (int mi = 0; mi < 2; mi++)
#pragma unroll
            for (int half = 0; half < 2; half++) {
                float m = -1e30f;
#pragma unroll
                for (int nf = 0; nf < 8; nf++)
                    m = fmaxf(m, fmaxf(acc[mi][nf][half * 2], acc[mi][nf][half * 2 + 1]));
                m = fmaxf(m, __shfl_xor_sync(0xffffffffu, m, 1));
                m = fmaxf(m, __shfl_xor_sync(0xffffffffu, m, 2));
                float s = 0.f;
#pragma unroll
                for (int nf = 0; nf < 8; nf++) {
                    float e0 = __expf(acc[mi][nf][half * 2] - m);
                    float e1 = __expf(acc[mi][nf][half * 2 + 1] - m);
                    acc[mi][nf][half * 2] = e0;
                    acc[mi][nf][half * 2 + 1] = e1;
                    s += e0 + e1;
                }
                s += __shfl_xor_sync(0xffffffffu, s, 1);
                s += __shfl_xor_sync(0xffffffffu, s, 2);
                float inv = 1.f / s;
#pragma unroll
                for (int nf = 0; nf < 8; nf++) {
                    acc[mi][nf][half * 2] *= inv;
                    acc[mi][nf][half * 2 + 1] *= inv;
                }
            }
    }

    const int r0 = bm + wm + (lane >> 2);
    const int c0 = bnn + wn + (lane & 3) * 2;
#pragma unroll
    for (int nf = 0; nf < 8; nf++) {
        int col = c0 + nf * 8;
#pragma unroll
        for (int mi = 0; mi < 2; mi++) {
            int row = r0 + mi * 16;
            float2 v0 = {acc[mi][nf][0], acc[mi][nf][1]};
            float2 v1 = {acc[mi][nf][2], acc[mi][nf][3]};
            *(float2*)(Cout + (size_t)row * 512 + col) = v0;
            *(float2*)(Cout + (size_t)(row + 8) * 512 + col) = v1;
        }
    }
}

// ---------------------------------------------------------------------------
// fp32 -> bf16 hi/lo split
// ---------------------------------------------------------------------------
__global__ __launch_bounds__(256) void split_k(
    const float* __restrict__ s, __nv_bfloat16* __restrict__ h,
    __nv_bfloat16* __restrict__ l, int n)
{
    int i = (blockIdx.x * 256 + threadIdx.x) * 4;
    if (i < n) {
        float4 v = *(const float4*)(s + i);
        __nv_bfloat16 h0 = __float2bfloat16(v.x), h1 = __float2bfloat16(v.y);
        __nv_bfloat16 h2 = __float2bfloat16(v.z), h3 = __float2bfloat16(v.w);
        __nv_bfloat162 hh0{h0, h1}, hh1{h2, h3};
        __nv_bfloat162 ll0{__float2bfloat16(v.x - __bfloat162float(h0)),
                           __float2bfloat16(v.y - __bfloat162float(h1))};
        __nv_bfloat162 ll1{__float2bfloat16(v.z - __bfloat162float(h2)),
                           __float2bfloat16(v.w - __bfloat162float(h3))};
        *(__nv_bfloat162*)(h + i) = hh0; *(__nv_bfloat162*)(h + i + 2) = hh1;
        *(__nv_bfloat162*)(l + i) = ll0; *(__nv_bfloat162*)(l + i + 2) = ll1;
    }
}

// ---------------------------------------------------------------------------
// context partials + k_sum partials (fp32); T slice of 128 per block
// ---------------------------------------------------------------------------
__global__ __launch_bounds__(256) void ctx_partial_k(
    const float* __restrict__ K, const float* __restrict__ V,
    float* __restrict__ ctxp, float* __restrict__ ksump)
{
    __shared__ float ks[32][65];
    __shared__ float vs[32][65];
    const int bh = blockIdx.x, b = bh >> 3, h = bh & 7;
    const int ts = blockIdx.y, tid = threadIdx.x;
    const int tx = tid & 15, ty = tid >> 4;
    const int col = tid & 63, trow = tid >> 6;

    float acc[4][4];
#pragma unroll
    for (int i = 0; i < 4; i++)
#pragma unroll
        for (int j = 0; j < 4; j++) acc[i][j] = 0.f;
    float ksacc[4] = {0.f, 0.f, 0.f, 0.f};
    const int rowbase = b * 4096 + ts * 128;

    for (int tt = 0; tt < 128; tt += 32) {
#pragma unroll
        for (int p = 0; p < 8; p++) {
            int t = trow + p * 4;
            size_t g = (size_t)(rowbase + tt + t) * 512 + h * 64 + col;
            ks[t][col] = K[g]; vs[t][col] = V[g];
        }
        __syncthreads();
#pragma unroll
        for (int t = 0; t < 32; t++) {
            float a[4], bb[4];
#pragma unroll
            for (int i = 0; i < 4; i++) a[i] = ks[t][ty * 4 + i];
#pragma unroll
            for (int j = 0; j < 4; j++) bb[j] = vs[t][tx * 4 + j];
#pragma unroll
            for (int i = 0; i < 4; i++)
#pragma unroll
                for (int j = 0; j < 4; j++) acc[i][j] += a[i] * bb[j];
            if (tx == 0)
#pragma unroll
                for (int i = 0; i < 4; i++) ksacc[i] += a[i];
        }
        __syncthreads();
    }
    float* cp = ctxp + (size_t)(ts * NBH + bh) * 4096;
#pragma unroll
    for (int i = 0; i < 4; i++)
#pragma unroll
        for (int j = 0; j < 4; j++)
            cp[(ty * 4 + i) * 64 + tx * 4 + j] = acc[i][j];
    if (tx == 0)
#pragma unroll
        for (int i = 0; i < 4; i++)
            ksump[(size_t)(ts * NBH + bh) * 64 + ty * 4 + i] = ksacc[i];
}

__global__ void reduce_ctx_k(const float* __restrict__ ctxp, float* __restrict__ ctx)
{
    int i = blockIdx.x * blockDim.x + threadIdx.x;
    if (i < NBH * 4096) {
        float s = 0.f;
#pragma unroll
        for (int p = 0; p < TSPLIT; p++) s += ctxp[(size_t)p * NBH * 4096 + i];
        ctx[i] = s;
    }
}
__global__ void reduce_ksum_k(const float* __restrict__ ksump, float* __restrict__ ksum)
{
    int i = blockIdx.x * blockDim.x + threadIdx.x;
    if (i < NBH * 64) {
        float s = 0.f;
#pragma unroll
        for (int p = 0; p < TSPLIT; p++) s += ksump[(size_t)p * NBH * 64 + i];
        ksum[i] = s;
    }
}

// ---------------------------------------------------------------------------
// out = (q @ ctx) * Dinv + q  -> written as bf16 hi/lo for final GEMM
// ---------------------------------------------------------------------------
__global__ __launch_bounds__(256) void attn_out_k(
    const float* __restrict__ Q, const float* __restrict__ ctx,
    const float* __restrict__ ksum,
    __nv_bfloat16* __restrict__ Oh, __nv_bfloat16* __restrict__ Ol)
{
    __shared__ float cs[64][64];
    __shared__ float qs[64][65];
    __shared__ float kss[64];
    const int bh = blockIdx.x, b = bh >> 3, h = bh & 7;
    const int tb = blockIdx.y, tid = threadIdx.x;

    const float* cg = ctx + (size_t)bh * 4096;
    for (int i = tid; i < 4096; i += 256) cs[i >> 6][i & 63] = cg[i];
    if (tid < 64) kss[tid] = ksum[bh * 64 + tid];

    const int rowbase = b * 4096 + tb * 64;
    const int col = tid & 63, rr = tid >> 6;
#pragma unroll
    for (int p = 0; p < 16; p++) {
        int r = rr + p * 4;
        qs[r][col] = Q[(size_t)(rowbase + r) * 512 + h * 64 + col];
    }
    __syncthreads();

    const int r = tid >> 2, e0 = (tid & 3) * 16;
    float acc[16];
#pragma unroll
    for (int j = 0; j < 16; j++) acc[j] = 0.f;
    float dv = 0.f;
#pragma unroll
    for (int d = 0; d < 64; d++) {
        float qv = qs[r][d];
        dv += qv * kss[d];
#pragma unroll
        for (int j = 0; j < 16; j++) acc[j] += qv * cs[d][e0 + j];
    }
    float Dinv = 1.f / dv;
    size_t base = (size_t)(rowbase + r) * 512 + h * 64 + e0;
#pragma unroll
    for (int j = 0; j < 16; j++) {
        float val = acc[j] * Dinv + qs[r][e0 + j];
        __nv_bfloat16 hh = __float2bfloat16(val);
        Oh[base + j] = hh;
        Ol[base + j] = __float2bfloat16(val - __bfloat162float(hh));
    }
}

// ---------------------------------------------------------------------------
extern "C" void kernel_launch(void* const* d_in, const int* in_sizes, int n_in,
                              void* d_out, int out_size)
{
    const float* x  = (const float*)d_in[0];
    const float* Wq = (const float*)d_in[1];
    const float* bq = (const float*)d_in[2];
    const float* Wk = (const float*)d_in[3];
    const float* bk = (const float*)d_in[4];
    const float* Wv = (const float*)d_in[5];
    const float* bv = (const float*)d_in[6];
    const float* Wp = (const float*)d_in[7];
    const float* bp = (const float*)d_in[8];
    float* out = (float*)d_out;

    float *q, *k, *v, *ctx, *ksum, *ctxp, *ksump;
    __nv_bfloat16 *xh, *xl, *oh, *ol, *wh, *wl;
    cudaGetSymbolAddress((void**)&q, g_q);
    cudaGetSymbolAddress((void**)&k, g_k);
    cudaGetSymbolAddress((void**)&v, g_v);
    cudaGetSymbolAddress((void**)&ctx, g_ctx);
    cudaGetSymbolAddress((void**)&ksum, g_ksum);
    cudaGetSymbolAddress((void**)&ctxp, g_ctxp);
    cudaGetSymbolAddress((void**)&ksump, g_ksump);
    cudaGetSymbolAddress((void**)&xh, g_xh);
    cudaGetSymbolAddress((void**)&xl, g_xl);
    cudaGetSymbolAddress((void**)&oh, g_oh);
    cudaGetSymbolAddress((void**)&ol, g_ol);
    cudaGetSymbolAddress((void**)&wh, g_wh);
    cudaGetSymbolAddress((void**)&wl, g_wl);

    cudaFuncSetAttribute(mma_gemm_k<true>, cudaFuncAttributeMaxDynamicSharedMemorySize,
                         SMEM_GEMM);
    cudaFuncSetAttribute(mma_gemm_k<false>, cudaFuncAttributeMaxDynamicSharedMemorySize,
                         SMEM_GEMM);

    const int NW = NDIM * NDIM;   // 262144

    // hi/lo conversions
    split_k<<<(M_TOT * NDIM) / 4 / 256, 256>>>(x, xh, xl, M_TOT * NDIM);
    split_k<<<NW / 4 / 256, 256>>>(Wq, wh + 0 * NW, wl + 0 * NW, NW);
    split_k<<<NW / 4 / 256, 256>>>(Wk, wh + 1 * NW, wl + 1 * NW, NW);
    split_k<<<NW / 4 / 256, 256>>>(Wv, wh + 2 * NW, wl + 2 * NW, NW);
    split_k<<<NW / 4 / 256, 256>>>(Wp, wh + 3 * NW, wl + 3 * NW, NW);

    // fused QKV GEMM + softmax epilogue (q,k) / bias (v)
    GArgs aqkv{xh, xl, wh, wl, bq, bk, bv, q, k, v};
    mma_gemm_k<true><<<dim3(12, 128), 256, SMEM_GEMM>>>(aqkv);

    ctx_partial_k<<<dim3(NBH, TSPLIT), 256>>>(k, v, ctxp, ksump);
    reduce_ctx_k<<<(NBH * 4096 + 255) / 256, 256>>>(ctxp, ctx);
    reduce_ksum_k<<<(NBH * 64 + 255) / 256, 256>>>(ksump, ksum);

    attn_out_k<<<dim3(NBH, 64), 256>>>(q, ctx, ksum, oh, ol);

    // output projection (plain)
    GArgs ap{oh, ol, wh + 3 * NW, wl + 3 * NW, bp, bp, bp, out, out, out};
    mma_gemm_k<false><<<dim3(4, 128), 256, SMEM_GEMM>>>(ap);
}